// round 1
// baseline (speedup 1.0000x reference)
#include <cuda_runtime.h>

#define N_AGENTS_MAX 50000
#define DIM 64

// Scratch (allocation rules forbid cudaMalloc; __device__ globals are the sanctioned path)
__device__ float g_sum[N_AGENTS_MAX * DIM];
__device__ float g_cnt[N_AGENTS_MAX];

// ---- packed f32x2 helpers (full-rate FFMA on sm_103a; 3-reg FFMA is half rate) ----
__device__ __forceinline__ unsigned long long pack2(float x) {
    unsigned long long r;
    unsigned int u = __float_as_uint(x);
    asm("mov.b64 %0, {%1, %1};" : "=l"(r) : "r"(u));
    return r;
}
__device__ __forceinline__ void fma2(unsigned long long& d, unsigned long long a, unsigned long long b) {
    asm("fma.rn.f32x2 %0, %1, %2, %0;" : "+l"(d) : "l"(a), "l"(b));
}
__device__ __forceinline__ float2 unpack2(unsigned long long v) {
    unsigned int lo, hi;
    asm("mov.b64 {%0, %1}, %2;" : "=r"(lo), "=r"(hi) : "l"(v));
    return make_float2(__uint_as_float(lo), __uint_as_float(hi));
}

// ---- kernel 0: zero scratch (graph replays must re-zero: atomics accumulate) ----
__global__ void zero_kernel(int na) {
    int i = blockIdx.x * blockDim.x + threadIdx.x;
    int stride = gridDim.x * blockDim.x;
    float4 z = make_float4(0.f, 0.f, 0.f, 0.f);
    float4* p = reinterpret_cast<float4*>(g_sum);
    int n4 = na * DIM / 4;
    for (int k = i; k < n4; k += stride) p[k] = z;
    for (int k = i; k < na; k += stride) g_cnt[k] = 0.f;
}

// ---- kernel 1: h = relu(X @ W1 + b1), segment-sum into g_sum, counts into g_cnt ----
// Block = 128 threads, 128 neighbors. smem: W1(4096f) + b1(64f) + X tile(128x65f) + seg(129i)
__global__ void __launch_bounds__(128) phi_kernel(
    const float* __restrict__ x, const float* __restrict__ w1,
    const float* __restrict__ b1, const int* __restrict__ seg, int nb)
{
    extern __shared__ float sm[];
    float* sW = sm;               // 4096
    float* sB = sW + 4096;        // 64
    float* sX = sB + 64;          // 128*65
    int*   sS = (int*)(sX + 128 * 65); // 129

    const int t  = threadIdx.x;
    const int n0 = blockIdx.x * 128;
    const int nb_local = min(128, nb - n0);

    for (int i = t; i < 4096; i += 128) sW[i] = w1[i];
    if (t < 64) sB[t] = b1[t];
    {
        const int total = nb_local * 64;
        const float* xg = x + (long long)n0 * 64;
        for (int i = t; i < total; i += 128)
            sX[(i >> 6) * 65 + (i & 63)] = xg[i];
    }
    {
        int g = n0 + t;
        sS[t] = (g < nb) ? seg[g] : -1;
        if (t == 0) {
            int g2 = n0 + 128;
            sS[128] = (g2 < nb) ? seg[g2] : -1;
        }
    }
    __syncthreads();

    // one neighbor per thread: 64-wide GEMV, accumulators packed f32x2
    if (t < nb_local) {
        unsigned long long acc[32];
#pragma unroll
        for (int j = 0; j < 32; j++) acc[j] = 0ull;
        const float* xr = sX + t * 65;
#pragma unroll 4
        for (int k = 0; k < 64; k++) {
            unsigned long long x2 = pack2(xr[k]);
            const float* wr = sW + k * 64;
#pragma unroll
            for (int j = 0; j < 16; j++) {
                ulonglong2 w = *reinterpret_cast<const ulonglong2*>(wr + j * 4);
                fma2(acc[2 * j],     x2, w.x);
                fma2(acc[2 * j + 1], x2, w.y);
            }
        }
        // bias + relu; overwrite own x row (only this thread reads it)
        float* hr = sX + t * 65;
#pragma unroll
        for (int j = 0; j < 32; j++) {
            float2 v = unpack2(acc[j]);
            hr[2 * j]     = fmaxf(v.x + sB[2 * j], 0.f);
            hr[2 * j + 1] = fmaxf(v.y + sB[2 * j + 1], 0.f);
        }
    }
    __syncthreads();

    // segmented reduction: thread -> (column j, half hh); run boundaries -> atomics.
    // sorted segment_ids => ~4-5 runs per 128 rows => ~25x fewer REDG than per-row atomics.
    {
        const int j  = t & 63;
        const int hh = t >> 6;
        const int ibeg = hh * 64;
        const int iend = min(ibeg + 64, nb_local);
        float acc = 0.f;
        float cnt = 0.f;
        for (int i = ibeg; i < iend; i++) {
            acc += sX[i * 65 + j];
            cnt += 1.f;
            int s = sS[i];
            bool flush = (i == iend - 1) || (sS[i + 1] != s);
            if (flush) {
                atomicAdd(&g_sum[s * DIM + j], acc);
                if (j == 0) atomicAdd(&g_cnt[s], cnt);
                acc = 0.f; cnt = 0.f;
            }
        }
    }
}

// ---- kernel 2: per-agent  t = sum@W2 + cnt*b2 ; r = relu(t@Rw1+Rb1) ; out = r@Rw2+Rb2 ----
__global__ void __launch_bounds__(128) rho_kernel(
    const float* __restrict__ w2, const float* __restrict__ b2,
    const float* __restrict__ rw1, const float* __restrict__ rb1,
    const float* __restrict__ rw2, const float* __restrict__ rb2,
    float* __restrict__ out, int na)
{
    extern __shared__ float sm[];
    float* sW   = sm;             // 4096 (W2, then rho_w1)
    float* sB   = sW + 4096;      // 64   (b2, then rho_b1)
    float* sWo  = sB + 64;        // 128  (rho_w2)
    float* sBo  = sWo + 128;      // 2    (rho_b2)
    float* sX   = sBo + 2;        // 128*65

    const int t  = threadIdx.x;
    const int a0 = blockIdx.x * 128;
    const int na_local = min(128, na - a0);

    for (int i = t; i < 4096; i += 128) sW[i] = w2[i];
    if (t < 64) sB[t] = b2[t];
    {
        const int total = na_local * 64;
        const float* xg = g_sum + (long long)a0 * 64;
        for (int i = t; i < total; i += 128)
            sX[(i >> 6) * 65 + (i & 63)] = xg[i];
    }
    __syncthreads();

    float cnt = (t < na_local) ? g_cnt[a0 + t] : 0.f;

    unsigned long long acc[32];
    // phase A: t_j = sum @ W2 + cnt * b2  -> write back into own row
    if (t < na_local) {
#pragma unroll
        for (int j = 0; j < 32; j++) acc[j] = 0ull;
        const float* xr = sX + t * 65;
#pragma unroll 4
        for (int k = 0; k < 64; k++) {
            unsigned long long x2 = pack2(xr[k]);
            const float* wr = sW + k * 64;
#pragma unroll
            for (int j = 0; j < 16; j++) {
                ulonglong2 w = *reinterpret_cast<const ulonglong2*>(wr + j * 4);
                fma2(acc[2 * j],     x2, w.x);
                fma2(acc[2 * j + 1], x2, w.y);
            }
        }
        float* hr = sX + t * 65;
#pragma unroll
        for (int j = 0; j < 32; j++) {
            float2 v = unpack2(acc[j]);
            hr[2 * j]     = v.x + cnt * sB[2 * j];
            hr[2 * j + 1] = v.y + cnt * sB[2 * j + 1];
        }
    }
    __syncthreads();

    // reload weights for rho
    for (int i = t; i < 4096; i += 128) sW[i] = rw1[i];
    if (t < 64)  sB[t]  = rb1[t];
    if (t < 128) sWo[t] = rw2[t];
    if (t < 2)   sBo[t] = rb2[t];
    __syncthreads();

    // phase B: r = relu(t @ rho_w1 + rho_b1) ; out = r @ rho_w2 + rho_b2
    if (t < na_local) {
#pragma unroll
        for (int j = 0; j < 32; j++) acc[j] = 0ull;
        const float* xr = sX + t * 65;
#pragma unroll 4
        for (int k = 0; k < 64; k++) {
            unsigned long long x2 = pack2(xr[k]);
            const float* wr = sW + k * 64;
#pragma unroll
            for (int j = 0; j < 16; j++) {
                ulonglong2 w = *reinterpret_cast<const ulonglong2*>(wr + j * 4);
                fma2(acc[2 * j],     x2, w.x);
                fma2(acc[2 * j + 1], x2, w.y);
            }
        }
        float o0 = sBo[0], o1 = sBo[1];
#pragma unroll
        for (int j = 0; j < 32; j++) {
            float2 v = unpack2(acc[j]);
            float r0 = fmaxf(v.x + sB[2 * j], 0.f);
            float r1 = fmaxf(v.y + sB[2 * j + 1], 0.f);
            o0 += r0 * sWo[4 * j]     + r1 * sWo[4 * j + 2];
            o1 += r0 * sWo[4 * j + 1] + r1 * sWo[4 * j + 3];
        }
        float2 o = make_float2(o0, o1);
        *reinterpret_cast<float2*>(out + (size_t)(a0 + t) * 2) = o;
    }
}

extern "C" void kernel_launch(void* const* d_in, const int* in_sizes, int n_in,
                              void* d_out, int out_size) {
    const float* neighbors = (const float*)d_in[0];
    const float* phi_w1 = (const float*)d_in[1];
    const float* phi_b1 = (const float*)d_in[2];
    const float* phi_w2 = (const float*)d_in[3];
    const float* phi_b2 = (const float*)d_in[4];
    const float* rho_w1 = (const float*)d_in[5];
    const float* rho_b1 = (const float*)d_in[6];
    const float* rho_w2 = (const float*)d_in[7];
    const float* rho_b2 = (const float*)d_in[8];
    const int*   seg    = (const int*)d_in[9];
    float* out = (float*)d_out;

    const int nb = in_sizes[0] / DIM;
    const int na = out_size / 2;

    const size_t PHI_SMEM = (4096 + 64 + 128 * 65) * sizeof(float) + 129 * sizeof(int);
    const size_t RHO_SMEM = (4096 + 64 + 128 + 2 + 128 * 65) * sizeof(float);
    cudaFuncSetAttribute(phi_kernel, cudaFuncAttributeMaxDynamicSharedMemorySize, (int)PHI_SMEM);
    cudaFuncSetAttribute(rho_kernel, cudaFuncAttributeMaxDynamicSharedMemorySize, (int)RHO_SMEM);

    zero_kernel<<<256, 256>>>(na);
    phi_kernel<<<(nb + 127) / 128, 128, PHI_SMEM>>>(neighbors, phi_w1, phi_b1, seg, nb);
    rho_kernel<<<(na + 127) / 128, 128, RHO_SMEM>>>(phi_w2, phi_b2, rho_w1, rho_b1,
                                                    rho_w2, rho_b2, out, na);
}

// round 2
// speedup vs baseline: 1.3265x; 1.3265x over previous
#include <cuda_runtime.h>

#define DIM 64
#define N_AGENTS_MAX 50000
#define XS 68  // smem row stride in floats: float4 accesses conflict-free (4l mod 32 per 8-lane phase)

__device__ float g_sum[N_AGENTS_MAX * DIM];
__device__ float g_cnt[N_AGENTS_MAX];

// ---- packed f32x2 helpers (FFMA2: full-rate fp32 on sm_103a, PTX-only) ----
__device__ __forceinline__ unsigned long long pack2(float x) {
    unsigned long long r;
    unsigned int u = __float_as_uint(x);
    asm("mov.b64 %0, {%1, %1};" : "=l"(r) : "r"(u));
    return r;
}
__device__ __forceinline__ void fma2(unsigned long long& d, unsigned long long a, unsigned long long b) {
    asm("fma.rn.f32x2 %0, %1, %2, %0;" : "+l"(d) : "l"(a), "l"(b));
}
__device__ __forceinline__ float2 unpack2(unsigned long long v) {
    unsigned int lo, hi;
    asm("mov.b64 {%0, %1}, %2;" : "=r"(lo), "=r"(hi) : "l"(v));
    return make_float2(__uint_as_float(lo), __uint_as_float(hi));
}

// ============================================================================
// phi: h = relu(X @ W1 + b1) per neighbor, then segmented sum into g_sum/g_cnt.
// 256 threads, 256 rows/block. Thread t: rows r0=(t&127), r1=r0+128 of the
// block tile, output half hf=(t>>7) (32 outputs = 16 f32x2 accs per row).
// ============================================================================
__global__ void __launch_bounds__(256, 2) phi_kernel(
    const float* __restrict__ x, const float* __restrict__ w1,
    const float* __restrict__ b1, const int* __restrict__ seg, int nb)
{
    extern __shared__ float sm[];
    float* sW = sm;                   // 4096 (W1, row-major [64,64])
    float* sB = sW + 4096;            // 64
    float* sX = sB + 64;              // 256 * 68
    int*   sS = (int*)(sX + 256 * XS);// 257

    const int t = threadIdx.x;
    const long long n0 = (long long)blockIdx.x * 256;
    const int nb_local = (int)min(256LL, (long long)nb - n0);

    for (int i = t; i < 4096; i += 256) sW[i] = w1[i];
    if (t < 64) sB[t] = b1[t];

    // stage X (float4, coalesced read, conflict-free strided write)
    {
        const float4* xg = (const float4*)(x + n0 * 64);
        const float4 z = make_float4(0.f, 0.f, 0.f, 0.f);
        for (int i = t; i < 256 * 16; i += 256) {
            int row = i >> 4, c = i & 15;
            float4 v = (row < nb_local) ? xg[i] : z;
            *(float4*)(sX + row * XS + c * 4) = v;
        }
    }
    {
        sS[t] = (t < nb_local) ? seg[n0 + t] : -1;
        if (t == 0) sS[256] = (n0 + 256 < (long long)nb) ? seg[n0 + 256] : -1;
    }
    __syncthreads();

    // ---- GEMV: 2 rows x 32 outputs per thread ----
    const int r0 = t & 127, hf = t >> 7;
    const int r1 = r0 + 128;
    const float* xr0 = sX + r0 * XS;
    const float* xr1 = sX + r1 * XS;
    const float* wb  = sW + hf * 32;

    unsigned long long acc0[16], acc1[16];
#pragma unroll
    for (int j = 0; j < 16; j++) { acc0[j] = 0ull; acc1[j] = 0ull; }

#pragma unroll 4
    for (int kq = 0; kq < 16; kq++) {
        float4 xa = *(const float4*)(xr0 + kq * 4);
        float4 xb = *(const float4*)(xr1 + kq * 4);
        const float* wr = wb + kq * 256;   // 4 k-rows of 64 floats
#pragma unroll
        for (int kk = 0; kk < 4; kk++) {
            unsigned long long xa2 = pack2(((const float*)&xa)[kk]);
            unsigned long long xb2 = pack2(((const float*)&xb)[kk]);
            const float* w = wr + kk * 64;
#pragma unroll
            for (int j = 0; j < 8; j++) {
                ulonglong2 ww = *(const ulonglong2*)(w + j * 4);   // warp-uniform -> broadcast
                fma2(acc0[2 * j],     xa2, ww.x);
                fma2(acc0[2 * j + 1], xa2, ww.y);
                fma2(acc1[2 * j],     xb2, ww.x);
                fma2(acc1[2 * j + 1], xb2, ww.y);
            }
        }
    }
    __syncthreads();

    // writeback h = relu(acc + b) as float4 (conflict-free)
    {
        float* h0 = sX + r0 * XS + hf * 32;
        float* h1 = sX + r1 * XS + hf * 32;
        const float* bh = sB + hf * 32;
#pragma unroll
        for (int j = 0; j < 8; j++) {
            float2 a = unpack2(acc0[2 * j]), b = unpack2(acc0[2 * j + 1]);
            float4 v0 = make_float4(fmaxf(a.x + bh[4 * j], 0.f),
                                    fmaxf(a.y + bh[4 * j + 1], 0.f),
                                    fmaxf(b.x + bh[4 * j + 2], 0.f),
                                    fmaxf(b.y + bh[4 * j + 3], 0.f));
            *(float4*)(h0 + 4 * j) = v0;
            float2 c = unpack2(acc1[2 * j]), d = unpack2(acc1[2 * j + 1]);
            float4 v1 = make_float4(fmaxf(c.x + bh[4 * j], 0.f),
                                    fmaxf(c.y + bh[4 * j + 1], 0.f),
                                    fmaxf(d.x + bh[4 * j + 2], 0.f),
                                    fmaxf(d.y + bh[4 * j + 3], 0.f));
            *(float4*)(h1 + 4 * j) = v1;
        }
    }
    __syncthreads();

    // ---- segmented reduction: thread -> (column j, row group g); sorted ids
    //      => few run boundaries => few atomics ----
    {
        const int j = t & 63, g = t >> 6;
        const int ibeg = g * 64;
        const int iend = min(ibeg + 64, nb_local);
        float acc = 0.f, cnt = 0.f;
        for (int i = ibeg; i < iend; i++) {
            acc += sX[i * XS + j];
            cnt += 1.f;
            bool flush = (i == iend - 1) || (sS[i + 1] != sS[i]);
            if (flush) {
                int s = sS[i];
                atomicAdd(&g_sum[s * DIM + j], acc);
                if (j == 0) atomicAdd(&g_cnt[s], cnt);
                acc = 0.f; cnt = 0.f;
            }
        }
    }
}

// ============================================================================
// rho: t = sum@W2 + cnt*b2 ; r = relu(t@rho_w1 + rho_b1) ; out = r@rho_w2 + rho_b2
// 256 threads, 128 agents/block, same half-split GEMV; partials combined in smem.
// ============================================================================
__global__ void __launch_bounds__(256) rho_kernel(
    const float* __restrict__ w2, const float* __restrict__ b2,
    const float* __restrict__ rw1, const float* __restrict__ rb1,
    const float* __restrict__ rw2, const float* __restrict__ rb2,
    float* __restrict__ out, int na)
{
    extern __shared__ float sm[];
    float* sW  = sm;               // 4096 (W2, then rho_w1)
    float* sB  = sW + 4096;        // 64   (b2, then rho_b1)
    float* sWo = sB + 64;          // 128  (rho_w2)
    float* sX  = sWo + 128;        // 128 * 68
    float* sP  = sX + 128 * XS;    // 512 partials

    const int t = threadIdx.x;
    const int a0 = blockIdx.x * 128;
    const int na_local = min(128, na - a0);

    for (int i = t; i < 4096; i += 256) sW[i] = w2[i];
    if (t < 64) sB[t] = b2[t];
    if (t < 128) sWo[t] = rw2[t];
    {
        const float4* xg = (const float4*)(g_sum + (long long)a0 * 64);
        const float4 z = make_float4(0.f, 0.f, 0.f, 0.f);
        for (int i = t; i < 128 * 16; i += 256) {
            int row = i >> 4, c = i & 15;
            float4 v = (row < na_local) ? xg[i] : z;
            *(float4*)(sX + row * XS + c * 4) = v;
        }
    }
    __syncthreads();

    const int a = t & 127, hf = t >> 7;
    const float* xr = sX + a * XS;
    const float* wb = sW + hf * 32;
    const float cnt = (a < na_local) ? g_cnt[a0 + a] : 0.f;

    unsigned long long acc[16];

    // ---- phase A: sum @ W2 (half) ----
#pragma unroll
    for (int j = 0; j < 16; j++) acc[j] = 0ull;
#pragma unroll 4
    for (int kq = 0; kq < 16; kq++) {
        float4 xa = *(const float4*)(xr + kq * 4);
        const float* wr = wb + kq * 256;
#pragma unroll
        for (int kk = 0; kk < 4; kk++) {
            unsigned long long x2 = pack2(((const float*)&xa)[kk]);
            const float* w = wr + kk * 64;
#pragma unroll
            for (int j = 0; j < 8; j++) {
                ulonglong2 ww = *(const ulonglong2*)(w + j * 4);
                fma2(acc[2 * j],     x2, ww.x);
                fma2(acc[2 * j + 1], x2, ww.y);
            }
        }
    }
    __syncthreads();

    // writeback t-vals (+cnt*b2), reload weights for rho layer 1
    {
        float* hr = sX + a * XS + hf * 32;
        const float* bh = sB + hf * 32;
#pragma unroll
        for (int j = 0; j < 8; j++) {
            float2 p = unpack2(acc[2 * j]), q = unpack2(acc[2 * j + 1]);
            float4 v = make_float4(p.x + cnt * bh[4 * j],
                                   p.y + cnt * bh[4 * j + 1],
                                   q.x + cnt * bh[4 * j + 2],
                                   q.y + cnt * bh[4 * j + 3]);
            *(float4*)(hr + 4 * j) = v;
        }
    }
    __syncthreads();
    for (int i = t; i < 4096; i += 256) sW[i] = rw1[i];
    if (t < 64) sB[t] = rb1[t];
    __syncthreads();

    // ---- phase B: r = relu(t @ rho_w1 + rho_b1), fold into out partials ----
#pragma unroll
    for (int j = 0; j < 16; j++) acc[j] = 0ull;
#pragma unroll 4
    for (int kq = 0; kq < 16; kq++) {
        float4 xa = *(const float4*)(xr + kq * 4);
        const float* wr = wb + kq * 256;
#pragma unroll
        for (int kk = 0; kk < 4; kk++) {
            unsigned long long x2 = pack2(((const float*)&xa)[kk]);
            const float* w = wr + kk * 64;
#pragma unroll
            for (int j = 0; j < 8; j++) {
                ulonglong2 ww = *(const ulonglong2*)(w + j * 4);
                fma2(acc[2 * j],     x2, ww.x);
                fma2(acc[2 * j + 1], x2, ww.y);
            }
        }
    }
    {
        const float* bh = sB + hf * 32;
        float o0 = 0.f, o1 = 0.f;
#pragma unroll
        for (int j = 0; j < 16; j++) {
            float2 v = unpack2(acc[j]);
            float r0 = fmaxf(v.x + bh[2 * j], 0.f);
            float r1 = fmaxf(v.y + bh[2 * j + 1], 0.f);
            int c = hf * 32 + 2 * j;               // global hidden index
            o0 += r0 * sWo[2 * c]     + r1 * sWo[2 * c + 2];
            o1 += r0 * sWo[2 * c + 1] + r1 * sWo[2 * c + 3];
        }
        sP[2 * t] = o0;
        sP[2 * t + 1] = o1;
    }
    __syncthreads();

    if (t < na_local) {
        float2 o = make_float2(sP[2 * t] + sP[2 * (t + 128)] + rb2[0],
                               sP[2 * t + 1] + sP[2 * (t + 128) + 1] + rb2[1]);
        *(float2*)(out + (size_t)(a0 + t) * 2) = o;
    }
}

extern "C" void kernel_launch(void* const* d_in, const int* in_sizes, int n_in,
                              void* d_out, int out_size) {
    const float* neighbors = (const float*)d_in[0];
    const float* phi_w1 = (const float*)d_in[1];
    const float* phi_b1 = (const float*)d_in[2];
    const float* phi_w2 = (const float*)d_in[3];
    const float* phi_b2 = (const float*)d_in[4];
    const float* rho_w1 = (const float*)d_in[5];
    const float* rho_b1 = (const float*)d_in[6];
    const float* rho_w2 = (const float*)d_in[7];
    const float* rho_b2 = (const float*)d_in[8];
    const int*   seg    = (const int*)d_in[9];
    float* out = (float*)d_out;

    const int nb = in_sizes[0] / DIM;
    const int na = out_size / 2;

    void* p_sum = nullptr;
    void* p_cnt = nullptr;
    cudaGetSymbolAddress(&p_sum, g_sum);
    cudaGetSymbolAddress(&p_cnt, g_cnt);
    cudaMemsetAsync(p_sum, 0, (size_t)na * DIM * sizeof(float));
    cudaMemsetAsync(p_cnt, 0, (size_t)na * sizeof(float));

    const size_t PHI_SMEM = (4096 + 64 + 256 * XS) * sizeof(float) + 257 * sizeof(int);
    const size_t RHO_SMEM = (4096 + 64 + 128 + 128 * XS + 512) * sizeof(float);
    cudaFuncSetAttribute(phi_kernel, cudaFuncAttributeMaxDynamicSharedMemorySize, (int)PHI_SMEM);
    cudaFuncSetAttribute(rho_kernel, cudaFuncAttributeMaxDynamicSharedMemorySize, (int)RHO_SMEM);

    phi_kernel<<<(nb + 255) / 256, 256, PHI_SMEM>>>(neighbors, phi_w1, phi_b1, seg, nb);
    rho_kernel<<<(na + 127) / 128, 256, RHO_SMEM>>>(phi_w2, phi_b2, rho_w1, rho_b1,
                                                    rho_w2, rho_b2, out, na);
}

// round 5
// speedup vs baseline: 2.2046x; 1.6619x over previous
#include <cuda_runtime.h>
#include <cstdint>

#define DIM 64
#define N_AGENTS_MAX 50000
#define XS 68

__device__ float g_sum[N_AGENTS_MAX * DIM];
__device__ float g_cnt[N_AGENTS_MAX];

// ---------------- phi smem layout (bytes) ----------------
// bf16 tiles: 128B per row (64 bf16), SW128 swizzle b ^ ((b>>3)&0x70)
#define OFF_WHI   0          // 8192  W1 hi  [64][64] bf16
#define OFF_WLO   8192       // 8192  W1 lo
#define OFF_XHI   16384      // 16384 X hi   [128][64] bf16
#define OFF_XLO   32768      // 16384 X lo
#define OFF_H     49152      // 34816 h fp32 [128][68]
#define OFF_BIAS  83968      // 256
#define OFF_SEG   84224      // 516
#define PHI_SMEM  84992

__device__ __forceinline__ uint32_t smem_u32(const void* p) {
    uint32_t a;
    asm("{ .reg .u64 t; cvta.to.shared.u64 t, %1; cvt.u32.u64 %0, t; }" : "=r"(a) : "l"(p));
    return a;
}

__device__ __forceinline__ void ldsm_x4(uint32_t* r, uint32_t addr) {
    asm volatile("ldmatrix.sync.aligned.m8n8.x4.shared.b16 {%0,%1,%2,%3}, [%4];"
        : "=r"(r[0]), "=r"(r[1]), "=r"(r[2]), "=r"(r[3]) : "r"(addr));
}
__device__ __forceinline__ void ldsm_x4_trans(uint32_t* r, uint32_t addr) {
    asm volatile("ldmatrix.sync.aligned.m8n8.x4.trans.shared.b16 {%0,%1,%2,%3}, [%4];"
        : "=r"(r[0]), "=r"(r[1]), "=r"(r[2]), "=r"(r[3]) : "r"(addr));
}
__device__ __forceinline__ void mma_bf16(float* d, const uint32_t* a, uint32_t b0, uint32_t b1) {
    asm volatile("mma.sync.aligned.m16n8k16.row.col.f32.bf16.bf16.f32 "
        "{%0,%1,%2,%3}, {%4,%5,%6,%7}, {%8,%9}, {%0,%1,%2,%3};"
        : "+f"(d[0]), "+f"(d[1]), "+f"(d[2]), "+f"(d[3])
        : "r"(a[0]), "r"(a[1]), "r"(a[2]), "r"(a[3]), "r"(b0), "r"(b1));
}

// split 4 fp32 -> bf16 hi (truncate) + bf16 lo (rn of remainder), store swizzled.
// row stride 128B; c4 indexes 8B groups (4 bf16). 16B-unit swizzle: unit ^= row&7.
__device__ __forceinline__ void split_store(unsigned char* hi_base, unsigned char* lo_base,
                                            int row, int c4, float4 v) {
    uint32_t x0 = __float_as_uint(v.x), x1 = __float_as_uint(v.y);
    uint32_t x2 = __float_as_uint(v.z), x3 = __float_as_uint(v.w);
    uint32_t hi01 = __byte_perm(x0, x1, 0x7632);
    uint32_t hi23 = __byte_perm(x2, x3, 0x7632);
    float l0 = v.x - __uint_as_float(x0 & 0xFFFF0000u);
    float l1 = v.y - __uint_as_float(x1 & 0xFFFF0000u);
    float l2 = v.z - __uint_as_float(x2 & 0xFFFF0000u);
    float l3 = v.w - __uint_as_float(x3 & 0xFFFF0000u);
    uint32_t lo01, lo23;
    asm("cvt.rn.bf16x2.f32 %0, %1, %2;" : "=r"(lo01) : "f"(l1), "f"(l0));
    asm("cvt.rn.bf16x2.f32 %0, %1, %2;" : "=r"(lo23) : "f"(l3), "f"(l2));
    uint32_t byte = (uint32_t)row * 128u
                  + ((((uint32_t)c4 >> 1) ^ ((uint32_t)row & 7u)) << 4)
                  + ((uint32_t)c4 & 1u) * 8u;
    *(uint2*)(hi_base + byte) = make_uint2(hi01, hi23);
    *(uint2*)(lo_base + byte) = make_uint2(lo01, lo23);
}

// ---- packed f32x2 helpers (rho kernel) ----
__device__ __forceinline__ unsigned long long pack2(float x) {
    unsigned long long r; unsigned int u = __float_as_uint(x);
    asm("mov.b64 %0, {%1, %1};" : "=l"(r) : "r"(u));
    return r;
}
__device__ __forceinline__ void fma2(unsigned long long& d, unsigned long long a, unsigned long long b) {
    asm("fma.rn.f32x2 %0, %1, %2, %0;" : "+l"(d) : "l"(a), "l"(b));
}
__device__ __forceinline__ float2 unpack2(unsigned long long v) {
    unsigned int lo, hi;
    asm("mov.b64 {%0, %1}, %2;" : "=r"(lo), "=r"(hi) : "l"(v));
    return make_float2(__uint_as_float(lo), __uint_as_float(hi));
}

// ============================================================================
// phi: h = relu(X @ W1 + b1) via 3-term bf16 mma.sync, then segmented sum
// (sorted ids -> run-boundary atomics) into g_sum/g_cnt.
// 256 threads = 8 warps; warp w computes rows [16w,16w+16) x 64 cols.
// ============================================================================
__global__ void __launch_bounds__(256, 2) phi_kernel(
    const float* __restrict__ x, const float* __restrict__ w1,
    const float* __restrict__ b1, const int* __restrict__ seg, int nb)
{
    extern __shared__ unsigned char smem[];
    const uint32_t sbase = smem_u32(smem);
    const int t = threadIdx.x;
    const int lane = t & 31, w = t >> 5;
    const long long n0 = (long long)blockIdx.x * 128;
    const int nb_local = (int)min(128LL, (long long)nb - n0);

    // stage W1 hi/lo (row-major [K=64][N=64], swizzled)
    for (int i = t; i < 1024; i += 256) {
        float4 v = ((const float4*)w1)[i];
        split_store(smem + OFF_WHI, smem + OFF_WLO, i >> 4, i & 15, v);
    }
    if (t < 64) ((float*)(smem + OFF_BIAS))[t] = b1[t];

    // stage X hi/lo ([128][64], swizzled); pad rows -> 0
    {
        const float4* xg = (const float4*)(x + n0 * 64);
        const float4 z = make_float4(0.f, 0.f, 0.f, 0.f);
#pragma unroll
        for (int it = 0; it < 8; it++) {
            int i = t + 256 * it;
            int row = i >> 4;
            float4 v = (row < nb_local) ? xg[i] : z;
            split_store(smem + OFF_XHI, smem + OFF_XLO, row, i & 15, v);
        }
    }
    int* sSeg = (int*)(smem + OFF_SEG);
    if (t < 128) sSeg[t] = (t < nb_local) ? seg[n0 + t] : -1;
    if (t == 0)  sSeg[128] = (n0 + 128 < (long long)nb) ? seg[n0 + 128] : -1;
    __syncthreads();

    // ---- mma: acc[nt][4], nt = 0..7 (8 n-tiles of 8) ----
    float acc[8][4];
#pragma unroll
    for (int i = 0; i < 8; i++) { acc[i][0] = acc[i][1] = acc[i][2] = acc[i][3] = 0.f; }

    const int w16 = w * 16;
    const int sub = lane >> 3;      // ldmatrix lane group 0..3
    const int l7 = lane & 7;

#pragma unroll
    for (int kc = 0; kc < 4; kc++) {
        // A x4: m0=rows0-7/k0-7, m1=rows8-15/k0-7, m2=rows0-7/k8-15, m3=rows8-15/k8-15
        uint32_t ah[4], al[4];
        {
            int r = w16 + l7 + ((sub & 1) << 3);
            uint32_t cb = (uint32_t)kc * 32u + ((uint32_t)(sub >> 1) << 4);
            uint32_t off = (uint32_t)r * 128u + ((((cb >> 4) ^ (uint32_t)(r & 7))) << 4);
            ldsm_x4(ah, sbase + OFF_XHI + off);
            ldsm_x4(al, sbase + OFF_XLO + off);
        }
        const int kk = kc * 16 + l7 + ((sub & 1) << 3);  // weight k-row for B groups 0/1
#pragma unroll
        for (int np = 0; np < 4; np++) {
            // B x4.trans covers nt=2np (regs 0,1) and nt=2np+1 (regs 2,3)
            uint32_t bh[4], bl[4];
            int ntc = 2 * np + (sub >> 1);
            uint32_t offB = (uint32_t)kk * 128u + ((uint32_t)(ntc ^ (kk & 7)) << 4);
            ldsm_x4_trans(bh, sbase + OFF_WHI + offB);
            ldsm_x4_trans(bl, sbase + OFF_WLO + offB);
            mma_bf16(acc[2 * np],     ah, bh[0], bh[1]);
            mma_bf16(acc[2 * np],     ah, bl[0], bl[1]);
            mma_bf16(acc[2 * np],     al, bh[0], bh[1]);
            mma_bf16(acc[2 * np + 1], ah, bh[2], bh[3]);
            mma_bf16(acc[2 * np + 1], ah, bl[2], bl[3]);
            mma_bf16(acc[2 * np + 1], al, bh[2], bh[3]);
        }
    }

    // ---- epilogue: bias + relu -> h (fp32, stride 68) ----
    {
        float* sH = (float*)(smem + OFF_H);
        const float* sB = (const float*)(smem + OFF_BIAS);
        int r0 = w16 + (lane >> 2);
        int c0 = (lane & 3) * 2;
#pragma unroll
        for (int nt = 0; nt < 8; nt++) {
            int c = nt * 8 + c0;
            float bx = sB[c], by = sB[c + 1];
            *(float2*)(sH + r0 * XS + c) =
                make_float2(fmaxf(acc[nt][0] + bx, 0.f), fmaxf(acc[nt][1] + by, 0.f));
            *(float2*)(sH + (r0 + 8) * XS + c) =
                make_float2(fmaxf(acc[nt][2] + bx, 0.f), fmaxf(acc[nt][3] + by, 0.f));
        }
    }
    __syncthreads();

    // ---- segmented reduction: 4 row-groups x 64 cols; sorted ids -> few atomics ----
    {
        const int j = t & 63, g = t >> 6;
        const int ibeg = g * 32;
        const int iend = min(ibeg + 32, nb_local);
        const float* sH = (const float*)(smem + OFF_H);
        float a = 0.f, cnt = 0.f;
        for (int i = ibeg; i < iend; i++) {
            a += sH[i * XS + j];
            cnt += 1.f;
            if (i == iend - 1 || sSeg[i + 1] != sSeg[i]) {
                int s = sSeg[i];
                atomicAdd(&g_sum[s * DIM + j], a);
                if (j == 0) atomicAdd(&g_cnt[s], cnt);
                a = 0.f; cnt = 0.f;
            }
        }
    }
}

// ============================================================================
// rho (unchanged, verified): t = sum@W2 + cnt*b2 ; r = relu(t@rw1+rb1) ;
// out = r@rw2+rb2.  256 threads, 128 agents/block, half-split GEMV.
// ============================================================================
__global__ void __launch_bounds__(256) rho_kernel(
    const float* __restrict__ w2, const float* __restrict__ b2,
    const float* __restrict__ rw1, const float* __restrict__ rb1,
    const float* __restrict__ rw2, const float* __restrict__ rb2,
    float* __restrict__ out, int na)
{
    extern __shared__ float sm[];
    float* sW  = sm;               // 4096
    float* sB  = sW + 4096;        // 64
    float* sWo = sB + 64;          // 128
    float* sX  = sWo + 128;        // 128 * 68
    float* sP  = sX + 128 * XS;    // 512

    const int t = threadIdx.x;
    const int a0 = blockIdx.x * 128;
    const int na_local = min(128, na - a0);

    for (int i = t; i < 4096; i += 256) sW[i] = w2[i];
    if (t < 64) sB[t] = b2[t];
    if (t < 128) sWo[t] = rw2[t];
    {
        const float4* xg = (const float4*)(g_sum + (long long)a0 * 64);
        const float4 z = make_float4(0.f, 0.f, 0.f, 0.f);
        for (int i = t; i < 128 * 16; i += 256) {
            int row = i >> 4, c = i & 15;
            float4 v = (row < na_local) ? xg[i] : z;
            *(float4*)(sX + row * XS + c * 4) = v;
        }
    }
    __syncthreads();

    const int a = t & 127, hf = t >> 7;
    const float* xr = sX + a * XS;
    const float* wb = sW + hf * 32;
    const float cnt = (a < na_local) ? g_cnt[a0 + a] : 0.f;

    unsigned long long acc[16];
#pragma unroll
    for (int j = 0; j < 16; j++) acc[j] = 0ull;
#pragma unroll 4
    for (int kq = 0; kq < 16; kq++) {
        float4 xa = *(const float4*)(xr + kq * 4);
        const float* wr = wb + kq * 256;
#pragma unroll
        for (int kk = 0; kk < 4; kk++) {
            unsigned long long x2 = pack2(((const float*)&xa)[kk]);
            const float* w = wr + kk * 64;
#pragma unroll
            for (int j = 0; j < 8; j++) {
                ulonglong2 ww = *(const ulonglong2*)(w + j * 4);
                fma2(acc[2 * j],     x2, ww.x);
                fma2(acc[2 * j + 1], x2, ww.y);
            }
        }
    }
    __syncthreads();
    {
        float* hr = sX + a * XS + hf * 32;
        const float* bh = sB + hf * 32;
#pragma unroll
        for (int j = 0; j < 8; j++) {
            float2 p = unpack2(acc[2 * j]), q = unpack2(acc[2 * j + 1]);
            float4 v = make_float4(p.x + cnt * bh[4 * j],
                                   p.y + cnt * bh[4 * j + 1],
                                   q.x + cnt * bh[4 * j + 2],
                                   q.y + cnt * bh[4 * j + 3]);
            *(float4*)(hr + 4 * j) = v;
        }
    }
    __syncthreads();
    for (int i = t; i < 4096; i += 256) sW[i] = rw1[i];
    if (t < 64) sB[t] = rb1[t];
    __syncthreads();

#pragma unroll
    for (int j = 0; j < 16; j++) acc[j] = 0ull;
#pragma unroll 4
    for (int kq = 0; kq < 16; kq++) {
        float4 xa = *(const float4*)(xr + kq * 4);
        const float* wr = wb + kq * 256;
#pragma unroll
        for (int kk = 0; kk < 4; kk++) {
            unsigned long long x2 = pack2(((const float*)&xa)[kk]);
            const float* w = wr + kk * 64;
#pragma unroll
            for (int j = 0; j < 8; j++) {
                ulonglong2 ww = *(const ulonglong2*)(w + j * 4);
                fma2(acc[2 * j],     x2, ww.x);
                fma2(acc[2 * j + 1], x2, ww.y);
            }
        }
    }
    {
        const float* bh = sB + hf * 32;
        float o0 = 0.f, o1 = 0.f;
#pragma unroll
        for (int j = 0; j < 16; j++) {
            float2 v = unpack2(acc[j]);
            float r0 = fmaxf(v.x + bh[2 * j], 0.f);
            float r1 = fmaxf(v.y + bh[2 * j + 1], 0.f);
            int c = hf * 32 + 2 * j;
            o0 += r0 * sWo[2 * c]     + r1 * sWo[2 * c + 2];
            o1 += r0 * sWo[2 * c + 1] + r1 * sWo[2 * c + 3];
        }
        sP[2 * t] = o0;
        sP[2 * t + 1] = o1;
    }
    __syncthreads();

    if (t < na_local) {
        float2 o = make_float2(sP[2 * t] + sP[2 * (t + 128)] + rb2[0],
                               sP[2 * t + 1] + sP[2 * (t + 128) + 1] + rb2[1]);
        *(float2*)(out + (size_t)(a0 + t) * 2) = o;
    }
}

extern "C" void kernel_launch(void* const* d_in, const int* in_sizes, int n_in,
                              void* d_out, int out_size) {
    const float* neighbors = (const float*)d_in[0];
    const float* phi_w1 = (const float*)d_in[1];
    const float* phi_b1 = (const float*)d_in[2];
    const float* phi_w2 = (const float*)d_in[3];
    const float* phi_b2 = (const float*)d_in[4];
    const float* rho_w1 = (const float*)d_in[5];
    const float* rho_b1 = (const float*)d_in[6];
    const float* rho_w2 = (const float*)d_in[7];
    const float* rho_b2 = (const float*)d_in[8];
    const int*   seg    = (const int*)d_in[9];
    float* out = (float*)d_out;

    const int nb = in_sizes[0] / DIM;
    const int na = out_size / 2;

    void* p_sum = nullptr;
    void* p_cnt = nullptr;
    cudaGetSymbolAddress(&p_sum, g_sum);
    cudaGetSymbolAddress(&p_cnt, g_cnt);
    cudaMemsetAsync(p_sum, 0, (size_t)na * DIM * sizeof(float));
    cudaMemsetAsync(p_cnt, 0, (size_t)na * sizeof(float));

    const size_t RHO_SMEM = (4096 + 64 + 128 + 128 * XS + 512) * sizeof(float);
    cudaFuncSetAttribute(phi_kernel, cudaFuncAttributeMaxDynamicSharedMemorySize, PHI_SMEM);
    cudaFuncSetAttribute(rho_kernel, cudaFuncAttributeMaxDynamicSharedMemorySize, (int)RHO_SMEM);

    const int ntiles = (nb + 127) / 128;
    phi_kernel<<<ntiles, 256, PHI_SMEM>>>(neighbors, phi_w1, phi_b1, seg, nb);
    rho_kernel<<<(na + 127) / 128, 256, RHO_SMEM>>>(phi_w2, phi_b2, rho_w1, rho_b1,
                                                    rho_w2, rho_b2, out, na);
}

// round 8
// speedup vs baseline: 2.9051x; 1.3178x over previous
#include <cuda_runtime.h>
#include <cuda_fp16.h>
#include <cstdint>

#define DIM 64
#define N_AGENTS_MAX 50000
#define XS 68

__device__ float g_sum[N_AGENTS_MAX * DIM];
__device__ float g_cnt[N_AGENTS_MAX];

// ---------------- phi smem layout (bytes) ----------------
// fp16 tiles: 128B per row (64 halves), swizzle b ^ ((b>>3)&0x70)
#define OFF_WHI   0          // 8192  W1 hi  [64][64] fp16
#define OFF_XHI   8192       // 16384 X hi   [128][64] fp16
#define OFF_XLO   24576      // 16384 X lo
#define OFF_H     40960      // 34816 h fp32 [128][68]
#define OFF_BIAS  75776      // 256
#define OFF_SEG   76032      // 516
#define PHI_SMEM  76800

__device__ __forceinline__ uint32_t smem_u32(const void* p) {
    uint32_t a;
    asm("{ .reg .u64 t; cvta.to.shared.u64 t, %1; cvt.u32.u64 %0, t; }" : "=r"(a) : "l"(p));
    return a;
}
__device__ __forceinline__ void ldsm_x4(uint32_t* r, uint32_t addr) {
    asm volatile("ldmatrix.sync.aligned.m8n8.x4.shared.b16 {%0,%1,%2,%3}, [%4];"
        : "=r"(r[0]), "=r"(r[1]), "=r"(r[2]), "=r"(r[3]) : "r"(addr));
}
__device__ __forceinline__ void ldsm_x4_trans(uint32_t* r, uint32_t addr) {
    asm volatile("ldmatrix.sync.aligned.m8n8.x4.trans.shared.b16 {%0,%1,%2,%3}, [%4];"
        : "=r"(r[0]), "=r"(r[1]), "=r"(r[2]), "=r"(r[3]) : "r"(addr));
}
__device__ __forceinline__ void mma_f16(float* d, const uint32_t* a, uint32_t b0, uint32_t b1) {
    asm volatile("mma.sync.aligned.m16n8k16.row.col.f32.f16.f16.f32 "
        "{%0,%1,%2,%3}, {%4,%5,%6,%7}, {%8,%9}, {%0,%1,%2,%3};"
        : "+f"(d[0]), "+f"(d[1]), "+f"(d[2]), "+f"(d[3])
        : "r"(a[0]), "r"(a[1]), "r"(a[2]), "r"(a[3]), "r"(b0), "r"(b1));
}

__device__ __forceinline__ uint32_t sw_off(int row, int c4) {
    return (uint32_t)row * 128u
         + ((((uint32_t)c4 >> 1) ^ ((uint32_t)row & 7u)) << 4)
         + ((uint32_t)c4 & 1u) * 8u;
}
// store hi-only fp16 (weights)
__device__ __forceinline__ void store_hi16(unsigned char* base, int row, int c4, float4 v) {
    __half2 h01 = __floats2half2_rn(v.x, v.y);
    __half2 h23 = __floats2half2_rn(v.z, v.w);
    uint2 u;
    u.x = *reinterpret_cast<uint32_t*>(&h01);
    u.y = *reinterpret_cast<uint32_t*>(&h23);
    *(uint2*)(base + sw_off(row, c4)) = u;
}
// split fp32 -> fp16 hi (rn) + fp16 lo (rn of remainder), store both swizzled
__device__ __forceinline__ void split_store16(unsigned char* hi_base, unsigned char* lo_base,
                                              int row, int c4, float4 v) {
    __half2 h01 = __floats2half2_rn(v.x, v.y);
    __half2 h23 = __floats2half2_rn(v.z, v.w);
    float2 b01 = __half22float2(h01);
    float2 b23 = __half22float2(h23);
    __half2 l01 = __floats2half2_rn(v.x - b01.x, v.y - b01.y);
    __half2 l23 = __floats2half2_rn(v.z - b23.x, v.w - b23.y);
    uint32_t byte = sw_off(row, c4);
    uint2 uh, ul;
    uh.x = *reinterpret_cast<uint32_t*>(&h01);
    uh.y = *reinterpret_cast<uint32_t*>(&h23);
    ul.x = *reinterpret_cast<uint32_t*>(&l01);
    ul.y = *reinterpret_cast<uint32_t*>(&l23);
    *(uint2*)(hi_base + byte) = uh;
    *(uint2*)(lo_base + byte) = ul;
}

// ---- packed f32x2 helpers (rho kernel) ----
__device__ __forceinline__ unsigned long long pack2(float x) {
    unsigned long long r; unsigned int u = __float_as_uint(x);
    asm("mov.b64 %0, {%1, %1};" : "=l"(r) : "r"(u));
    return r;
}
__device__ __forceinline__ void fma2(unsigned long long& d, unsigned long long a, unsigned long long b) {
    asm("fma.rn.f32x2 %0, %1, %2, %0;" : "+l"(d) : "l"(a), "l"(b));
}
__device__ __forceinline__ float2 unpack2(unsigned long long v) {
    unsigned int lo, hi;
    asm("mov.b64 {%0, %1}, %2;" : "=r"(lo), "=r"(hi) : "l"(v));
    return make_float2(__uint_as_float(lo), __uint_as_float(hi));
}

// ============================================================================
// phi (persistent): h = relu(X @ W1 + b1) via 2-term fp16 mma.sync
// (x = xh + xl exactly; only W truncation error ~2^-12 remains), then
// segmented sum (sorted ids -> run-boundary atomics) into g_sum/g_cnt.
// 256 threads = 8 warps; warp wp computes rows [16wp,16wp+16) x 64 cols.
// ============================================================================
__global__ void __launch_bounds__(256, 2) phi_kernel(
    const float* __restrict__ x, const float* __restrict__ w1,
    const float* __restrict__ b1, const int* __restrict__ seg, int nb)
{
    extern __shared__ unsigned char smem[];
    const uint32_t sbase = smem_u32(smem);
    const int t = threadIdx.x;
    const int lane = t & 31, wp = t >> 5;
    const int ntiles = (nb + 127) >> 7;
    int* sSeg = (int*)(smem + OFF_SEG);

    // ---- stage W1 hi + bias ONCE ----
    for (int i = t; i < 1024; i += 256)
        store_hi16(smem + OFF_WHI, i >> 4, i & 15, ((const float4*)w1)[i]);
    if (t < 64) ((float*)(smem + OFF_BIAS))[t] = b1[t];

    // ---- prefetch first tile into registers ----
    float4 xp[8];
    int sp, spx;
    {
        long long n0 = (long long)blockIdx.x * 128;
        int nbl = (int)min(128LL, (long long)nb - n0);
        const float4* xg = (const float4*)(x + n0 * 64);
        const float4 z = make_float4(0.f, 0.f, 0.f, 0.f);
#pragma unroll
        for (int it = 0; it < 8; it++) {
            int i = t + 256 * it;
            xp[it] = ((i >> 4) < nbl) ? xg[i] : z;
        }
        sp  = (t < 128 && t < nbl) ? seg[n0 + t] : -1;
        spx = (n0 + 128 < (long long)nb) ? seg[n0 + 128] : -1;
    }

    const int w16 = wp * 16;
    const int sub = lane >> 3, l7 = lane & 7;

    for (int tile = blockIdx.x; tile < ntiles; tile += gridDim.x) {
        const long long n0 = (long long)tile * 128;
        const int nb_local = (int)min(128LL, (long long)nb - n0);

        // ---- store staged tile (X hi/lo + seg) ----
#pragma unroll
        for (int it = 0; it < 8; it++) {
            int i = t + 256 * it;
            split_store16(smem + OFF_XHI, smem + OFF_XLO, i >> 4, i & 15, xp[it]);
        }
        if (t < 128) sSeg[t] = sp;
        if (t == 0)  sSeg[128] = spx;
        __syncthreads();

        // ---- mma: 2-term fp16, acc[nt][4], nt = 0..7 ----
        float acc[8][4];
#pragma unroll
        for (int i = 0; i < 8; i++) { acc[i][0] = acc[i][1] = acc[i][2] = acc[i][3] = 0.f; }

#pragma unroll
        for (int kc = 0; kc < 4; kc++) {
            uint32_t ah[4], al[4];
            {
                int r = w16 + l7 + ((sub & 1) << 3);
                uint32_t cb = (uint32_t)kc * 32u + ((uint32_t)(sub >> 1) << 4);
                uint32_t off = (uint32_t)r * 128u + ((((cb >> 4) ^ (uint32_t)(r & 7))) << 4);
                ldsm_x4(ah, sbase + OFF_XHI + off);
                ldsm_x4(al, sbase + OFF_XLO + off);
            }
            const int kk = kc * 16 + l7 + ((sub & 1) << 3);
#pragma unroll
            for (int np = 0; np < 4; np++) {
                uint32_t bh[4];
                int ntc = 2 * np + (sub >> 1);
                uint32_t offB = (uint32_t)kk * 128u + ((uint32_t)(ntc ^ (kk & 7)) << 4);
                ldsm_x4_trans(bh, sbase + OFF_WHI + offB);
                mma_f16(acc[2 * np],     ah, bh[0], bh[1]);
                mma_f16(acc[2 * np],     al, bh[0], bh[1]);
                mma_f16(acc[2 * np + 1], ah, bh[2], bh[3]);
                mma_f16(acc[2 * np + 1], al, bh[2], bh[3]);
            }
        }

        // ---- epilogue: bias + relu -> h (fp32, stride 68) ----
        {
            float* sH = (float*)(smem + OFF_H);
            const float* sB = (const float*)(smem + OFF_BIAS);
            int r0 = w16 + (lane >> 2);
            int c0 = (lane & 3) * 2;
#pragma unroll
            for (int nt = 0; nt < 8; nt++) {
                int c = nt * 8 + c0;
                float bx = sB[c], by = sB[c + 1];
                *(float2*)(sH + r0 * XS + c) =
                    make_float2(fmaxf(acc[nt][0] + bx, 0.f), fmaxf(acc[nt][1] + by, 0.f));
                *(float2*)(sH + (r0 + 8) * XS + c) =
                    make_float2(fmaxf(acc[nt][2] + bx, 0.f), fmaxf(acc[nt][3] + by, 0.f));
            }
        }

        // ---- prefetch next tile (LDG hidden behind reduction phase) ----
        {
            int next = tile + gridDim.x;
            if (next < ntiles) {
                long long m0 = (long long)next * 128;
                int nbl = (int)min(128LL, (long long)nb - m0);
                const float4* xg = (const float4*)(x + m0 * 64);
                const float4 z = make_float4(0.f, 0.f, 0.f, 0.f);
#pragma unroll
                for (int it = 0; it < 8; it++) {
                    int i = t + 256 * it;
                    xp[it] = ((i >> 4) < nbl) ? xg[i] : z;
                }
                sp  = (t < 128 && t < nbl) ? seg[m0 + t] : -1;
                spx = (m0 + 128 < (long long)nb) ? seg[m0 + 128] : -1;
            }
        }
        __syncthreads();

        // ---- segmented reduction: 8 row-groups x 64 cols (2 col-owners each);
        //      wait: 256 threads = 4 groups of 64 cols over 32 rows each ----
        {
            const int j = t & 63, g = t >> 6;
            const int ibeg = g * 32;
            const int iend = min(ibeg + 32, nb_local);
            const float* sH = (const float*)(smem + OFF_H);
            float a = 0.f, cnt = 0.f;
            for (int i = ibeg; i < iend; i++) {
                a += sH[i * XS + j];
                cnt += 1.f;
                if (i == iend - 1 || sSeg[i + 1] != sSeg[i]) {
                    int s = sSeg[i];
                    atomicAdd(&g_sum[s * DIM + j], a);
                    if (j == 0) atomicAdd(&g_cnt[s], cnt);
                    a = 0.f; cnt = 0.f;
                }
            }
        }
        __syncthreads();   // h/seg consumed before next iteration overwrites
    }
}

// ============================================================================
// rho (unchanged, verified): t = sum@W2 + cnt*b2 ; r = relu(t@rw1+rb1) ;
// out = r@rw2+rb2.  256 threads, 128 agents/block, half-split GEMV.
// ============================================================================
__global__ void __launch_bounds__(256) rho_kernel(
    const float* __restrict__ w2, const float* __restrict__ b2,
    const float* __restrict__ rw1, const float* __restrict__ rb1,
    const float* __restrict__ rw2, const float* __restrict__ rb2,
    float* __restrict__ out, int na)
{
    extern __shared__ float sm[];
    float* sW  = sm;               // 4096
    float* sB  = sW + 4096;        // 64
    float* sWo = sB + 64;          // 128
    float* sX  = sWo + 128;        // 128 * 68
    float* sP  = sX + 128 * XS;    // 512

    const int t = threadIdx.x;
    const int a0 = blockIdx.x * 128;
    const int na_local = min(128, na - a0);

    for (int i = t; i < 4096; i += 256) sW[i] = w2[i];
    if (t < 64) sB[t] = b2[t];
    if (t < 128) sWo[t] = rw2[t];
    {
        const float4* xg = (const float4*)(g_sum + (long long)a0 * 64);
        const float4 z = make_float4(0.f, 0.f, 0.f, 0.f);
        for (int i = t; i < 128 * 16; i += 256) {
            int row = i >> 4, c = i & 15;
            float4 v = (row < na_local) ? xg[i] : z;
            *(float4*)(sX + row * XS + c * 4) = v;
        }
    }
    __syncthreads();

    const int a = t & 127, hf = t >> 7;
    const float* xr = sX + a * XS;
    const float* wb = sW + hf * 32;
    const float cnt = (a < na_local) ? g_cnt[a0 + a] : 0.f;

    unsigned long long acc[16];
#pragma unroll
    for (int j = 0; j < 16; j++) acc[j] = 0ull;
#pragma unroll 4
    for (int kq = 0; kq < 16; kq++) {
        float4 xa = *(const float4*)(xr + kq * 4);
        const float* wr = wb + kq * 256;
#pragma unroll
        for (int kk = 0; kk < 4; kk++) {
            unsigned long long x2 = pack2(((const float*)&xa)[kk]);
            const float* w = wr + kk * 64;
#pragma unroll
            for (int j = 0; j < 8; j++) {
                ulonglong2 ww = *(const ulonglong2*)(w + j * 4);
                fma2(acc[2 * j],     x2, ww.x);
                fma2(acc[2 * j + 1], x2, ww.y);
            }
        }
    }
    __syncthreads();
    {
        float* hr = sX + a * XS + hf * 32;
        const float* bh = sB + hf * 32;
#pragma unroll
        for (int j = 0; j < 8; j++) {
            float2 p = unpack2(acc[2 * j]), q = unpack2(acc[2 * j + 1]);
            float4 v = make_float4(p.x + cnt * bh[4 * j],
                                   p.y + cnt * bh[4 * j + 1],
                                   q.x + cnt * bh[4 * j + 2],
                                   q.y + cnt * bh[4 * j + 3]);
            *(float4*)(hr + 4 * j) = v;
        }
    }
    __syncthreads();
    for (int i = t; i < 4096; i += 256) sW[i] = rw1[i];
    if (t < 64) sB[t] = rb1[t];
    __syncthreads();

#pragma unroll
    for (int j = 0; j < 16; j++) acc[j] = 0ull;
#pragma unroll 4
    for (int kq = 0; kq < 16; kq++) {
        float4 xa = *(const float4*)(xr + kq * 4);
        const float* wr = wb + kq * 256;
#pragma unroll
        for (int kk = 0; kk < 4; kk++) {
            unsigned long long x2 = pack2(((const float*)&xa)[kk]);
            const float* w = wr + kk * 64;
#pragma unroll
            for (int j = 0; j < 8; j++) {
                ulonglong2 ww = *(const ulonglong2*)(w + j * 4);
                fma2(acc[2 * j],     x2, ww.x);
                fma2(acc[2 * j + 1], x2, ww.y);
            }
        }
    }
    {
        const float* bh = sB + hf * 32;
        float o0 = 0.f, o1 = 0.f;
#pragma unroll
        for (int j = 0; j < 16; j++) {
            float2 v = unpack2(acc[j]);
            float r0 = fmaxf(v.x + bh[2 * j], 0.f);
            float r1 = fmaxf(v.y + bh[2 * j + 1], 0.f);
            int c = hf * 32 + 2 * j;
            o0 += r0 * sWo[2 * c]     + r1 * sWo[2 * c + 2];
            o1 += r0 * sWo[2 * c + 1] + r1 * sWo[2 * c + 3];
        }
        sP[2 * t] = o0;
        sP[2 * t + 1] = o1;
    }
    __syncthreads();

    if (t < na_local) {
        float2 o = make_float2(sP[2 * t] + sP[2 * (t + 128)] + rb2[0],
                               sP[2 * t + 1] + sP[2 * (t + 128) + 1] + rb2[1]);
        *(float2*)(out + (size_t)(a0 + t) * 2) = o;
    }
}

extern "C" void kernel_launch(void* const* d_in, const int* in_sizes, int n_in,
                              void* d_out, int out_size) {
    const float* neighbors = (const float*)d_in[0];
    const float* phi_w1 = (const float*)d_in[1];
    const float* phi_b1 = (const float*)d_in[2];
    const float* phi_w2 = (const float*)d_in[3];
    const float* phi_b2 = (const float*)d_in[4];
    const float* rho_w1 = (const float*)d_in[5];
    const float* rho_b1 = (const float*)d_in[6];
    const float* rho_w2 = (const float*)d_in[7];
    const float* rho_b2 = (const float*)d_in[8];
    const int*   seg    = (const int*)d_in[9];
    float* out = (float*)d_out;

    const int nb = in_sizes[0] / DIM;
    const int na = out_size / 2;

    void* p_sum = nullptr;
    void* p_cnt = nullptr;
    cudaGetSymbolAddress(&p_sum, g_sum);
    cudaGetSymbolAddress(&p_cnt, g_cnt);
    cudaMemsetAsync(p_sum, 0, (size_t)na * DIM * sizeof(float));
    cudaMemsetAsync(p_cnt, 0, (size_t)na * sizeof(float));

    const size_t RHO_SMEM = (4096 + 64 + 128 + 128 * XS + 512) * sizeof(float);
    cudaFuncSetAttribute(phi_kernel, cudaFuncAttributeMaxDynamicSharedMemorySize, PHI_SMEM);
    cudaFuncSetAttribute(rho_kernel, cudaFuncAttributeMaxDynamicSharedMemorySize, (int)RHO_SMEM);

    const int ntiles = (nb + 127) / 128;
    int grid = 2 * 148;
    if (grid > ntiles) grid = ntiles;

    phi_kernel<<<grid, 256, PHI_SMEM>>>(neighbors, phi_w1, phi_b1, seg, nb);
    rho_kernel<<<(na + 127) / 128, 256, RHO_SMEM>>>(phi_w2, phi_b2, rho_w1, rho_b1,
                                                    rho_w2, rho_b2, out, na);
}

// round 10
// speedup vs baseline: 4.6412x; 1.5976x over previous
#include <cuda_runtime.h>
#include <cuda_fp16.h>
#include <cstdint>

#define DIM 64
#define N_AGENTS_MAX 50000
#define XS 68

__device__ float g_sum[N_AGENTS_MAX * DIM];
__device__ float g_cnt[N_AGENTS_MAX];

// ---------------- phi smem layout (bytes) ----------------
#define OFF_WHI   0          // 8192  W1 hi  [64][64] fp16
#define OFF_XHI   8192       // 16384 X hi   [128][64] fp16
#define OFF_XLO   24576      // 16384 X lo
#define OFF_H     40960      // 34816 h fp32 [128][68]
#define OFF_BIAS  75776      // 256
#define OFF_SEG   76032      // 516
#define PHI_SMEM  76800

// ---------------- rho smem layout (bytes) ----------------
#define R_W2      0          // 8192  W2 hi fp16
#define R_RW1     8192       // 8192  rho_w1 hi fp16
#define R_XHI     16384      // 16384
#define R_XLO     32768      // 16384
#define R_B2      49152      // 256
#define R_RB1     49408      // 256
#define R_RW2     49664      // 512
#define R_CNT     50176      // 512
#define RHO_SMEM  50688

__device__ __forceinline__ uint32_t smem_u32(const void* p) {
    uint32_t a;
    asm("{ .reg .u64 t; cvta.to.shared.u64 t, %1; cvt.u32.u64 %0, t; }" : "=r"(a) : "l"(p));
    return a;
}
__device__ __forceinline__ void ldsm_x4(uint32_t* r, uint32_t addr) {
    asm volatile("ldmatrix.sync.aligned.m8n8.x4.shared.b16 {%0,%1,%2,%3}, [%4];"
        : "=r"(r[0]), "=r"(r[1]), "=r"(r[2]), "=r"(r[3]) : "r"(addr));
}
__device__ __forceinline__ void ldsm_x4_trans(uint32_t* r, uint32_t addr) {
    asm volatile("ldmatrix.sync.aligned.m8n8.x4.trans.shared.b16 {%0,%1,%2,%3}, [%4];"
        : "=r"(r[0]), "=r"(r[1]), "=r"(r[2]), "=r"(r[3]) : "r"(addr));
}
__device__ __forceinline__ void mma_f16(float* d, const uint32_t* a, uint32_t b0, uint32_t b1) {
    asm volatile("mma.sync.aligned.m16n8k16.row.col.f32.f16.f16.f32 "
        "{%0,%1,%2,%3}, {%4,%5,%6,%7}, {%8,%9}, {%0,%1,%2,%3};"
        : "+f"(d[0]), "+f"(d[1]), "+f"(d[2]), "+f"(d[3])
        : "r"(a[0]), "r"(a[1]), "r"(a[2]), "r"(a[3]), "r"(b0), "r"(b1));
}

__device__ __forceinline__ uint32_t sw_off(int row, int c4) {
    return (uint32_t)row * 128u
         + ((((uint32_t)c4 >> 1) ^ ((uint32_t)row & 7u)) << 4)
         + ((uint32_t)c4 & 1u) * 8u;
}
__device__ __forceinline__ void store_hi16(unsigned char* base, int row, int c4, float4 v) {
    __half2 h01 = __floats2half2_rn(v.x, v.y);
    __half2 h23 = __floats2half2_rn(v.z, v.w);
    uint2 u;
    u.x = *reinterpret_cast<uint32_t*>(&h01);
    u.y = *reinterpret_cast<uint32_t*>(&h23);
    *(uint2*)(base + sw_off(row, c4)) = u;
}
__device__ __forceinline__ void split_store16(unsigned char* hi_base, unsigned char* lo_base,
                                              int row, int c4, float4 v) {
    __half2 h01 = __floats2half2_rn(v.x, v.y);
    __half2 h23 = __floats2half2_rn(v.z, v.w);
    float2 b01 = __half22float2(h01);
    float2 b23 = __half22float2(h23);
    __half2 l01 = __floats2half2_rn(v.x - b01.x, v.y - b01.y);
    __half2 l23 = __floats2half2_rn(v.z - b23.x, v.w - b23.y);
    uint32_t byte = sw_off(row, c4);
    uint2 uh, ul;
    uh.x = *reinterpret_cast<uint32_t*>(&h01);
    uh.y = *reinterpret_cast<uint32_t*>(&h23);
    ul.x = *reinterpret_cast<uint32_t*>(&l01);
    ul.y = *reinterpret_cast<uint32_t*>(&l23);
    *(uint2*)(hi_base + byte) = uh;
    *(uint2*)(lo_base + byte) = ul;
}
// store one (v0,v1) pair at even col c: split hi/lo half2
__device__ __forceinline__ void store_pair16(unsigned char* hi_base, unsigned char* lo_base,
                                             int row, int c, float v0, float v1) {
    __half2 h = __floats2half2_rn(v0, v1);
    float2 hf = __half22float2(h);
    __half2 l = __floats2half2_rn(v0 - hf.x, v1 - hf.y);
    uint32_t byte = (uint32_t)row * 128u
                  + ((((uint32_t)c >> 3) ^ ((uint32_t)row & 7u)) << 4)
                  + ((uint32_t)c & 7u) * 2u;
    *(uint32_t*)(hi_base + byte) = *reinterpret_cast<uint32_t*>(&h);
    *(uint32_t*)(lo_base + byte) = *reinterpret_cast<uint32_t*>(&l);
}

// 2-term fp16 mma over one 128x64 tile: A frags from xhi/xlo, B frags from w.
// acc[8][4]; warp wp covers rows [16wp,16wp+16).
__device__ __forceinline__ void mma_tile(float acc[8][4], uint32_t sbase,
                                         uint32_t off_xhi, uint32_t off_xlo, uint32_t off_w,
                                         int w16, int sub, int l7) {
#pragma unroll
    for (int i = 0; i < 8; i++) { acc[i][0] = acc[i][1] = acc[i][2] = acc[i][3] = 0.f; }
#pragma unroll
    for (int kc = 0; kc < 4; kc++) {
        uint32_t ah[4], al[4];
        {
            int r = w16 + l7 + ((sub & 1) << 3);
            uint32_t cb = (uint32_t)kc * 32u + ((uint32_t)(sub >> 1) << 4);
            uint32_t off = (uint32_t)r * 128u + ((((cb >> 4) ^ (uint32_t)(r & 7))) << 4);
            ldsm_x4(ah, sbase + off_xhi + off);
            ldsm_x4(al, sbase + off_xlo + off);
        }
        const int kk = kc * 16 + l7 + ((sub & 1) << 3);
#pragma unroll
        for (int np = 0; np < 4; np++) {
            uint32_t bh[4];
            int ntc = 2 * np + (sub >> 1);
            uint32_t offB = (uint32_t)kk * 128u + ((uint32_t)(ntc ^ (kk & 7)) << 4);
            ldsm_x4_trans(bh, sbase + off_w + offB);
            mma_f16(acc[2 * np],     ah, bh[0], bh[1]);
            mma_f16(acc[2 * np],     al, bh[0], bh[1]);
            mma_f16(acc[2 * np + 1], ah, bh[2], bh[3]);
            mma_f16(acc[2 * np + 1], al, bh[2], bh[3]);
        }
    }
}

// ============================================================================
// phi (persistent): h = relu(X @ W1 + b1) via 2-term fp16 mma, then WARP-LOCAL
// segmented reduction (each warp owns its 16 rows; batched LDS; ballot mask).
// ============================================================================
__global__ void __launch_bounds__(256, 2) phi_kernel(
    const float* __restrict__ x, const float* __restrict__ w1,
    const float* __restrict__ b1, const int* __restrict__ seg, int nb)
{
    extern __shared__ unsigned char smem[];
    const uint32_t sbase = smem_u32(smem);
    const int t = threadIdx.x;
    const int lane = t & 31, wp = t >> 5;
    const int ntiles = (nb + 127) >> 7;
    int* sSeg = (int*)(smem + OFF_SEG);

    for (int i = t; i < 1024; i += 256)
        store_hi16(smem + OFF_WHI, i >> 4, i & 15, ((const float4*)w1)[i]);
    if (t < 64) ((float*)(smem + OFF_BIAS))[t] = b1[t];

    // prefetch first tile
    float4 xp[8];
    int sp;
    {
        long long n0 = (long long)blockIdx.x * 128;
        int nbl = (int)min(128LL, (long long)nb - n0);
        const float4* xg = (const float4*)(x + n0 * 64);
        const float4 z = make_float4(0.f, 0.f, 0.f, 0.f);
#pragma unroll
        for (int it = 0; it < 8; it++) {
            int i = t + 256 * it;
            xp[it] = ((i >> 4) < nbl) ? xg[i] : z;
        }
        sp = (t < 128 && t < nbl) ? seg[n0 + t] : -1;
    }

    const int w16 = wp * 16;
    const int sub = lane >> 3, l7 = lane & 7;

    for (int tile = blockIdx.x; tile < ntiles; tile += gridDim.x) {
#pragma unroll
        for (int it = 0; it < 8; it++) {
            int i = t + 256 * it;
            split_store16(smem + OFF_XHI, smem + OFF_XLO, i >> 4, i & 15, xp[it]);
        }
        if (t < 128) sSeg[t] = sp;
        if (t == 0)  sSeg[128] = -1;   // bit15 is force-flushed; value irrelevant
        __syncthreads();               // sync1: tiles + seg visible to all warps

        float acc[8][4];
        mma_tile(acc, sbase, OFF_XHI, OFF_XLO, OFF_WHI, w16, sub, l7);

        // epilogue: bias + relu -> own-warp rows of sH
        {
            float* sH = (float*)(smem + OFF_H);
            const float* sB = (const float*)(smem + OFF_BIAS);
            int r0 = w16 + (lane >> 2);
            int c0 = (lane & 3) * 2;
#pragma unroll
            for (int nt = 0; nt < 8; nt++) {
                int c = nt * 8 + c0;
                float bx = sB[c], by = sB[c + 1];
                *(float2*)(sH + r0 * XS + c) =
                    make_float2(fmaxf(acc[nt][0] + bx, 0.f), fmaxf(acc[nt][1] + by, 0.f));
                *(float2*)(sH + (r0 + 8) * XS + c) =
                    make_float2(fmaxf(acc[nt][2] + bx, 0.f), fmaxf(acc[nt][3] + by, 0.f));
            }
        }

        // prefetch next tile (overlaps reduction)
        {
            int next = tile + gridDim.x;
            if (next < ntiles) {
                long long m0 = (long long)next * 128;
                int nbl = (int)min(128LL, (long long)nb - m0);
                const float4* xg = (const float4*)(x + m0 * 64);
                const float4 z = make_float4(0.f, 0.f, 0.f, 0.f);
#pragma unroll
                for (int it = 0; it < 8; it++) {
                    int i = t + 256 * it;
                    xp[it] = ((i >> 4) < nbl) ? xg[i] : z;
                }
                sp = (t < 128 && t < nbl) ? seg[m0 + t] : -1;
            }
        }
        __syncwarp();   // own-warp h rows visible

        // ---- warp-local segmented reduction over rows [w16, w16+16) ----
        {
            uint32_t bmask;
            {
                bool b = false;
                if (lane < 16) b = sSeg[w16 + lane] != sSeg[w16 + lane + 1];
                bmask = __ballot_sync(0xffffffffu, b);
            }
            const float* sH = (const float*)(smem + OFF_H);
#pragma unroll
            for (int half = 0; half < 2; half++) {
                const int j = lane + 32 * half;
                float v[16];
#pragma unroll
                for (int i = 0; i < 16; i++) v[i] = sH[(w16 + i) * XS + j];
                float a = 0.f;
#pragma unroll
                for (int i = 0; i < 16; i++) {
                    a += v[i];
                    if (i == 15 || ((bmask >> i) & 1)) {
                        int s = sSeg[w16 + i];
                        if (s >= 0) atomicAdd(&g_sum[s * DIM + j], a);
                        a = 0.f;
                    }
                }
            }
            if (lane == 0) {
                float c = 0.f;
#pragma unroll
                for (int i = 0; i < 16; i++) {
                    c += 1.f;
                    if (i == 15 || ((bmask >> i) & 1)) {
                        int s = sSeg[w16 + i];
                        if (s >= 0) atomicAdd(&g_cnt[s], c);
                        c = 0.f;
                    }
                }
            }
        }
        __syncthreads();   // sync2: seg/X consumed before next tile's stores
    }
}

// ============================================================================
// rho via fp16 2-term mma: t = sum@W2 + cnt*b2 ; r = relu(t@rw1+rb1) ;
// out = r@rw2+rb2 (folded into phase-B epilogue with shfl reduce).
// 256 threads, 128 agents/block.
// ============================================================================
__global__ void __launch_bounds__(256, 2) rho_kernel(
    const float* __restrict__ w2, const float* __restrict__ b2,
    const float* __restrict__ rw1, const float* __restrict__ rb1,
    const float* __restrict__ rw2, const float* __restrict__ rb2,
    float* __restrict__ out, int na)
{
    extern __shared__ unsigned char smem[];
    const uint32_t sbase = smem_u32(smem);
    const int t = threadIdx.x;
    const int lane = t & 31, wp = t >> 5;
    const int a0 = blockIdx.x * 128;
    const int na_local = min(128, na - a0);

    // stage weights hi, biases, rw2, cnt, and split X = g_sum tile
    for (int i = t; i < 1024; i += 256) {
        store_hi16(smem + R_W2,  i >> 4, i & 15, ((const float4*)w2)[i]);
        store_hi16(smem + R_RW1, i >> 4, i & 15, ((const float4*)rw1)[i]);
    }
    if (t < 64)  { ((float*)(smem + R_B2))[t] = b2[t]; ((float*)(smem + R_RB1))[t] = rb1[t]; }
    if (t < 128) ((float*)(smem + R_RW2))[t] = rw2[t];
    if (t < 128) ((float*)(smem + R_CNT))[t] = (t < na_local) ? g_cnt[a0 + t] : 0.f;
    {
        const float4* xg = (const float4*)(g_sum + (long long)a0 * 64);
        const float4 z = make_float4(0.f, 0.f, 0.f, 0.f);
        for (int i = t; i < 128 * 16; i += 256) {
            float4 v = ((i >> 4) < na_local) ? xg[i] : z;
            split_store16(smem + R_XHI, smem + R_XLO, i >> 4, i & 15, v);
        }
    }
    __syncthreads();

    const int w16 = wp * 16;
    const int sub = lane >> 3, l7 = lane & 7;
    const int r0 = w16 + (lane >> 2);
    const int c0 = (lane & 3) * 2;

    float acc[8][4];

    // ---- phase A: t = X @ W2 (+ cnt*b2 in epilogue) ----
    mma_tile(acc, sbase, R_XHI, R_XLO, R_W2, w16, sub, l7);
    __syncwarp();
    {
        const float* sB2 = (const float*)(smem + R_B2);
        const float* sCnt = (const float*)(smem + R_CNT);
        float cA = sCnt[r0], cB = sCnt[r0 + 8];
#pragma unroll
        for (int nt = 0; nt < 8; nt++) {
            int c = nt * 8 + c0;
            float bx = sB2[c], by = sB2[c + 1];
            store_pair16(smem + R_XHI, smem + R_XLO, r0, c,
                         acc[nt][0] + cA * bx, acc[nt][1] + cA * by);
            store_pair16(smem + R_XHI, smem + R_XLO, r0 + 8, c,
                         acc[nt][2] + cB * bx, acc[nt][3] + cB * by);
        }
    }
    __syncwarp();   // own-warp rows only: warp-local exchange

    // ---- phase B: r = relu(t @ rw1 + rb1); out = r @ rw2 + rb2 ----
    mma_tile(acc, sbase, R_XHI, R_XLO, R_RW1, w16, sub, l7);
    {
        const float* sRB1 = (const float*)(smem + R_RB1);
        const float* sRW2 = (const float*)(smem + R_RW2);
        float o0a = 0.f, o1a = 0.f, o0b = 0.f, o1b = 0.f;
#pragma unroll
        for (int nt = 0; nt < 8; nt++) {
            int c = nt * 8 + c0;
            float b0 = sRB1[c], b1v = sRB1[c + 1];
            float w00 = sRW2[2 * c],     w01 = sRW2[2 * c + 1];
            float w10 = sRW2[2 * c + 2], w11 = sRW2[2 * c + 3];
            float r00 = fmaxf(acc[nt][0] + b0,  0.f);
            float r01 = fmaxf(acc[nt][1] + b1v, 0.f);
            float r10 = fmaxf(acc[nt][2] + b0,  0.f);
            float r11 = fmaxf(acc[nt][3] + b1v, 0.f);
            o0a += r00 * w00 + r01 * w10;
            o1a += r00 * w01 + r01 * w11;
            o0b += r10 * w00 + r11 * w10;
            o1b += r10 * w01 + r11 * w11;
        }
#pragma unroll
        for (int m = 1; m <= 2; m <<= 1) {
            o0a += __shfl_xor_sync(0xffffffffu, o0a, m);
            o1a += __shfl_xor_sync(0xffffffffu, o1a, m);
            o0b += __shfl_xor_sync(0xffffffffu, o0b, m);
            o1b += __shfl_xor_sync(0xffffffffu, o1b, m);
        }
        if ((lane & 3) == 0) {
            float c0b = rb2[0], c1b = rb2[1];
            if (r0 < na_local)
                *(float2*)(out + (size_t)(a0 + r0) * 2) = make_float2(o0a + c0b, o1a + c1b);
            if (r0 + 8 < na_local)
                *(float2*)(out + (size_t)(a0 + r0 + 8) * 2) = make_float2(o0b + c0b, o1b + c1b);
        }
    }
}

extern "C" void kernel_launch(void* const* d_in, const int* in_sizes, int n_in,
                              void* d_out, int out_size) {
    const float* neighbors = (const float*)d_in[0];
    const float* phi_w1 = (const float*)d_in[1];
    const float* phi_b1 = (const float*)d_in[2];
    const float* phi_w2 = (const float*)d_in[3];
    const float* phi_b2 = (const float*)d_in[4];
    const float* rho_w1 = (const float*)d_in[5];
    const float* rho_b1 = (const float*)d_in[6];
    const float* rho_w2 = (const float*)d_in[7];
    const float* rho_b2 = (const float*)d_in[8];
    const int*   seg    = (const int*)d_in[9];
    float* out = (float*)d_out;

    const int nb = in_sizes[0] / DIM;
    const int na = out_size / 2;

    void* p_sum = nullptr;
    void* p_cnt = nullptr;
    cudaGetSymbolAddress(&p_sum, g_sum);
    cudaGetSymbolAddress(&p_cnt, g_cnt);
    cudaMemsetAsync(p_sum, 0, (size_t)na * DIM * sizeof(float));
    cudaMemsetAsync(p_cnt, 0, (size_t)na * sizeof(float));

    cudaFuncSetAttribute(phi_kernel, cudaFuncAttributeMaxDynamicSharedMemorySize, PHI_SMEM);
    cudaFuncSetAttribute(rho_kernel, cudaFuncAttributeMaxDynamicSharedMemorySize, RHO_SMEM);

    const int ntiles = (nb + 127) / 128;
    int grid = 2 * 148;
    if (grid > ntiles) grid = ntiles;

    phi_kernel<<<grid, 256, PHI_SMEM>>>(neighbors, phi_w1, phi_b1, seg, nb);
    rho_kernel<<<(na + 127) / 128, 256, RHO_SMEM>>>(phi_w2, phi_b2, rho_w1, rho_b1,
                                                    rho_w2, rho_b2, out, na);
}